// round 14
// baseline (speedup 1.0000x reference)
#include <cuda_runtime.h>
#include <cuda_bf16.h>
#include <cstdint>

// Router: logits = x @ W^T, hybrid dual-engine GEMM:
//   warps 0-7  (2/SMSP): split-bf16 mma.sync (3 terms) for tokens 0-63
//   warps 8-11 (1/SMSP): exact fp32 f32x2 FFMA for tokens 64-127
// All staging via cp.async (zero STS). W pre-converted (bf16 hi/lo) and
// pre-transposed (fp32) once per launch.
// Outputs fp32: mask[T*64] | idx[T*2] | router_probs[T*64] | probs[T*64]

#define THREADS 384
#define TM 128
#define CK 64
#define NCH (2048 / CK)   // 32
#define NSTG 3
#define APITCH 272        // A fp32 row pitch bytes (68 words; 16B-aligned)
#define WTPITCH 288       // transposed-W fp32 row pitch bytes (72 words)
#define BSTR 144          // B bf16 row stride bytes

// per-stage layout (bytes)
#define A_O   0           // 128*272 = 34816
#define WT_O  34816       // 64*288 = 18432
#define BHI_O 53248       // 9216
#define BLO_O 62464       // 9216
#define BUFSZ 71680
#define SMEMB (NSTG * BUFSZ)   // 215040
#define LS 68

typedef unsigned long long ull;

__device__ __nv_bfloat16 g_Whi[64 * 2048];
__device__ __nv_bfloat16 g_Wlo[64 * 2048];
__device__ float g_WT[2048 * 64];   // W transposed: [k][expert]

__device__ __forceinline__ uint32_t smem_u32(const void* p) {
    uint32_t a;
    asm("{ .reg .u64 t; cvta.to.shared.u64 t, %1; cvt.u32.u64 %0, t; }"
        : "=r"(a) : "l"(p));
    return a;
}

__device__ __forceinline__ void ldm4(uint32_t* r, uint32_t addr) {
    asm volatile("ldmatrix.sync.aligned.m8n8.x4.shared.b16 {%0,%1,%2,%3}, [%4];"
        : "=r"(r[0]), "=r"(r[1]), "=r"(r[2]), "=r"(r[3]) : "r"(addr));
}

__device__ __forceinline__ void mma16816(float* d, const uint32_t* a,
                                         uint32_t b0, uint32_t b1) {
    asm("mma.sync.aligned.m16n8k16.row.col.f32.bf16.bf16.f32 "
        "{%0,%1,%2,%3}, {%4,%5,%6,%7}, {%8,%9}, {%0,%1,%2,%3};"
        : "+f"(d[0]), "+f"(d[1]), "+f"(d[2]), "+f"(d[3])
        : "r"(a[0]), "r"(a[1]), "r"(a[2]), "r"(a[3]), "r"(b0), "r"(b1));
}

__device__ __forceinline__ ull dup2(float w) {
    ull r;
    asm("mov.b64 %0, {%1, %1};" : "=l"(r) : "f"(w));
    return r;
}
__device__ __forceinline__ void fma2(ull& d, ull a, ull b) {
    asm("fma.rn.f32x2 %0, %1, %2, %0;" : "+l"(d) : "l"(a), "l"(b));
}

__device__ __forceinline__ void split2(float2 v, uint32_t& hi, uint32_t& lo) {
    asm("cvt.rn.bf16x2.f32 %0, %1, %2;" : "=r"(hi) : "f"(v.y), "f"(v.x));
    const float h0 = __uint_as_float(hi << 16);
    const float h1 = __uint_as_float(hi & 0xffff0000u);
    asm("cvt.rn.bf16x2.f32 %0, %1, %2;" : "=r"(lo) : "f"(v.y - h1), "f"(v.x - h0));
}
__device__ __forceinline__ void split4(float4 v, ull& H, ull& L) {
    uint32_t h0, h1, l0, l1;
    split2(make_float2(v.x, v.y), h0, l0);
    split2(make_float2(v.z, v.w), h1, l1);
    asm("mov.b64 %0, {%1, %2};" : "=l"(H) : "r"(h0), "r"(h1));
    asm("mov.b64 %0, {%1, %2};" : "=l"(L) : "r"(l0), "r"(l1));
}

__device__ __forceinline__ void cpa16(uint32_t dst, const void* src) {
    asm volatile("cp.async.cg.shared.global [%0], [%1], 16;"
                 :: "r"(dst), "l"(src) : "memory");
}
__device__ __forceinline__ void cpa16z(uint32_t dst, const void* src, int sz) {
    asm volatile("cp.async.cg.shared.global [%0], [%1], 16, %2;"
                 :: "r"(dst), "l"(src), "r"(sz) : "memory");
}

// ---- pre-kernel: W -> bf16 hi/lo + fp32 transpose ----
__global__ void __launch_bounds__(256)
wprep_kernel(const float* __restrict__ W)
{
    const int i = blockIdx.x * 256 + threadIdx.x;   // 0..32767 float4s
    const float4 v = reinterpret_cast<const float4*>(W)[i];
    ull H, L;
    split4(v, H, L);
    reinterpret_cast<ull*>(g_Whi)[i] = H;
    reinterpret_cast<ull*>(g_Wlo)[i] = L;
    const int fi = i * 4;
    const int e = fi >> 11;         // expert
    const int k = fi & 2047;        // k base (4-aligned)
    g_WT[(k + 0) * 64 + e] = v.x;
    g_WT[(k + 1) * 64 + e] = v.y;
    g_WT[(k + 2) * 64 + e] = v.z;
    g_WT[(k + 3) * 64 + e] = v.w;
}

__global__ void __launch_bounds__(THREADS, 1)
router_kernel(const float* __restrict__ x, float* __restrict__ out, int T)
{
    extern __shared__ __align__(128) char dsm[];
    const uint32_t sb = smem_u32(dsm);

    const int tid = threadIdx.x;
    const int wid = tid >> 5;
    const int lane = tid & 31;
    const int row0 = blockIdx.x * TM;

    auto issue_stage = [&](int kc, uint32_t off) {
        const int k0 = kc * CK;
        // A fp32: 128 rows x 16 float4 = 2048 ops
#pragma unroll
        for (int i = 0; i < 6; i++) {
            const int f = i * THREADS + tid;
            if (f < 2048) {
                const int ar = f >> 4;
                const int grow = row0 + ar;
                const int gsrc = (grow < T) ? grow : 0;
                cpa16z(sb + off + A_O + (uint32_t)(ar * APITCH + (f & 15) * 16),
                       x + (size_t)gsrc * 2048 + k0 + (f & 15) * 4,
                       (grow < T) ? 16 : 0);
            }
        }
        // WT fp32: 64 k-rows x 16 float4 = 1024 ops
#pragma unroll
        for (int i = 0; i < 3; i++) {
            const int f = i * THREADS + tid;
            if (f < 1024) {
                const int rr = f >> 4;
                const int cc = f & 15;
                cpa16(sb + off + WT_O + (uint32_t)(rr * WTPITCH + cc * 16),
                      g_WT + (size_t)(k0 + rr) * 64 + cc * 4);
            }
        }
        // B bf16 hi/lo: 64 rows x 8 x 16B each
#pragma unroll
        for (int i = 0; i < 2; i++) {
            const int f = i * THREADS + tid;
            if (f < 512) {
                const int rr = f >> 3;
                const int cc = f & 7;
                cpa16(sb + off + BHI_O + (uint32_t)(rr * BSTR + cc * 16),
                      g_Whi + (size_t)rr * 2048 + k0 + cc * 8);
                cpa16(sb + off + BLO_O + (uint32_t)(rr * BSTR + cc * 16),
                      g_Wlo + (size_t)rr * 2048 + k0 + cc * 8);
            }
        }
    };

    issue_stage(0, 0);
    asm volatile("cp.async.commit_group;" ::: "memory");
    issue_stage(1, BUFSZ);
    asm volatile("cp.async.commit_group;" ::: "memory");

    // tensor warp coords (wid 0-7): 16tok x 32exp tile, tokens 0-63
    const int sr = (wid >> 1) * 16;
    const int eh = (wid & 1) * 32;
    const int r = lane >> 2;
    const int c2 = (lane & 3) * 2;
    const uint32_t b_base = (uint32_t)((eh + (lane & 7) + ((lane >> 4) & 1) * 8) * BSTR
                                       + (((lane >> 3) & 1) << 4));
    float acc[4][4];
#pragma unroll
    for (int g = 0; g < 4; g++)
#pragma unroll
        for (int j = 0; j < 4; j++) acc[g][j] = 0.f;

    // ffma warp coords (wid 8-11): 16tok x 64exp, tokens 64-127
    const int fw = wid - 8;
    const int pg = lane >> 3;          // 0..3
    const int eg = lane & 7;           // expert group eg*8..+7
    const int ftok = 64 + fw * 16 + pg;   // tokens ftok + ti*4
    ull facc[4][4];                    // [ti][expert-pair j]
#pragma unroll
    for (int ti = 0; ti < 4; ti++)
#pragma unroll
        for (int j = 0; j < 4; j++) facc[ti][j] = 0ULL;

    for (int c = 0; c < NCH; c++) {
        if (c != NCH - 1) asm volatile("cp.async.wait_group 1;" ::: "memory");
        else              asm volatile("cp.async.wait_group 0;" ::: "memory");
        __syncthreads();

        if (c + 2 < NCH) {
            issue_stage(c + 2, (uint32_t)((c + 2) % NSTG) * BUFSZ);
            asm volatile("cp.async.commit_group;" ::: "memory");
        }

        const uint32_t off = (uint32_t)(c % NSTG) * BUFSZ;
        const uint32_t tb = sb + off;

        if (wid < 8) {
            // ================= TENSOR STREAM =================
            const char* Ab = dsm + off + A_O;
#pragma unroll
            for (int kk = 0; kk < 4; kk++) {
                uint32_t ah[4], al[4];
                const char* p = Ab + (sr + r) * APITCH + (kk * 16 + c2) * 4;
                split2(*reinterpret_cast<const float2*>(p),               ah[0], al[0]);
                split2(*reinterpret_cast<const float2*>(p + 8 * APITCH),  ah[1], al[1]);
                split2(*reinterpret_cast<const float2*>(p + 32),          ah[2], al[2]);
                split2(*reinterpret_cast<const float2*>(p + 8 * APITCH + 32), ah[3], al[3]);

                uint32_t vh[2][4], vl[2][4];
                const uint32_t ko = (uint32_t)kk * 32;
#pragma unroll
                for (int jp = 0; jp < 2; jp++) {
                    ldm4(vh[jp], tb + BHI_O + b_base + (uint32_t)(jp * 16 * BSTR) + ko);
                    ldm4(vl[jp], tb + BLO_O + b_base + (uint32_t)(jp * 16 * BSTR) + ko);
                }
#pragma unroll
                for (int jp = 0; jp < 2; jp++)
#pragma unroll
                    for (int tt = 0; tt < 2; tt++) {
                        float* dd = acc[jp * 2 + tt];
                        mma16816(dd, ah, vh[jp][tt * 2], vh[jp][tt * 2 + 1]);
                        mma16816(dd, ah, vl[jp][tt * 2], vl[jp][tt * 2 + 1]);
                        mma16816(dd, al, vh[jp][tt * 2], vh[jp][tt * 2 + 1]);
                    }
            }
        } else {
            // ================= FFMA STREAM (exact fp32) =================
            const char* Ab = dsm + off + A_O + ftok * APITCH;
            const char* Wb = dsm + off + WT_O + eg * 32;
#pragma unroll 8
            for (int k = 0; k < CK; k++) {
                ull xd[4];
#pragma unroll
                for (int ti = 0; ti < 4; ti++)
                    xd[ti] = dup2(*reinterpret_cast<const float*>(
                        Ab + ti * 4 * APITCH + k * 4));
                const ulonglong2 qa = *reinterpret_cast<const ulonglong2*>(Wb + k * WTPITCH);
                const ulonglong2 qb = *reinterpret_cast<const ulonglong2*>(Wb + k * WTPITCH + 16);
                const ull wp[4] = {qa.x, qa.y, qb.x, qb.y};
#pragma unroll
                for (int ti = 0; ti < 4; ti++)
#pragma unroll
                    for (int j = 0; j < 4; j++) fma2(facc[ti][j], xd[ti], wp[j]);
            }
        }
    }

    __syncthreads();

    // ---- dump logits to smem [TM][LS] ----
    float* lg = reinterpret_cast<float*>(dsm);
    if (wid < 8) {
        const int r1 = sr + (lane >> 2);
#pragma unroll
        for (int g = 0; g < 4; g++) {
            const int ec = eh + (g >> 1) * 16 + (g & 1) * 8 + 2 * (lane & 3);
            *reinterpret_cast<float2*>(lg + r1 * LS + ec) =
                make_float2(acc[g][0], acc[g][1]);
            *reinterpret_cast<float2*>(lg + (r1 + 8) * LS + ec) =
                make_float2(acc[g][2], acc[g][3]);
        }
    } else {
#pragma unroll
        for (int ti = 0; ti < 4; ti++) {
            const int t = ftok + ti * 4;
#pragma unroll
            for (int j = 0; j < 4; j++) {
                const ull v = facc[ti][j];
                *reinterpret_cast<float2*>(lg + t * LS + eg * 8 + j * 2) =
                    make_float2(__uint_as_float((uint32_t)v),
                                __uint_as_float((uint32_t)(v >> 32)));
            }
        }
    }
    __syncthreads();

    // ---- epilogue: one thread = one token (threads 0..127) ----
    if (tid >= TM) return;
    const int row = row0 + tid;
    if (row >= T) return;

    float l[64];
#pragma unroll
    for (int e = 0; e < 64; e += 4) {
        const float4 v = *reinterpret_cast<const float4*>(lg + tid * LS + e);
        l[e] = v.x; l[e + 1] = v.y; l[e + 2] = v.z; l[e + 3] = v.w;
    }

    float m1 = -3.402823466e38f, m2 = -3.402823466e38f;
    int i1 = 0, i2 = 0;
#pragma unroll
    for (int e = 0; e < 64; e++) {
        const float v = l[e];
        if (v > m1) { m2 = m1; i2 = i1; m1 = v; i1 = e; }
        else if (v > m2) { m2 = v; i2 = e; }
    }

    float s = 0.f;
    float p[64];
#pragma unroll
    for (int e = 0; e < 64; e++) {
        p[e] = __expf(l[e] - m1);
        s += p[e];
    }
    const float inv = 1.0f / s;

    const float p1 = p[i1] * inv;
    const float p2 = p[i2] * inv;
    const float rs = 1.0f / (p1 + p2);

    const size_t Tz = (size_t)T;
    float* mask = out;
    float* idxo = out + Tz * 64;
    float* rp   = out + Tz * 64 + Tz * 2;
    float* pr   = out + Tz * 64 + Tz * 2 + Tz * 64;
    const size_t gt = (size_t)row;

#pragma unroll
    for (int e = 0; e < 64; e += 4) {
        float4 pv4, m4, r4;
        float* pvp = &pv4.x; float* mp = &m4.x; float* rpp = &r4.x;
#pragma unroll
        for (int j = 0; j < 4; j++) {
            const int ee = e + j;
            const float pv = p[ee] * inv;
            const bool sel = (ee == i1) | (ee == i2);
            pvp[j] = pv;
            mp[j] = sel ? 1.0f : 0.0f;
            rpp[j] = sel ? pv * rs : 0.0f;
        }
        *reinterpret_cast<float4*>(pr + gt * 64 + e) = pv4;
        *reinterpret_cast<float4*>(mask + gt * 64 + e) = m4;
        *reinterpret_cast<float4*>(rp + gt * 64 + e) = r4;
    }
    idxo[gt * 2 + 0] = (float)i1;
    idxo[gt * 2 + 1] = (float)i2;
}

extern "C" void kernel_launch(void* const* d_in, const int* in_sizes, int n_in,
                              void* d_out, int out_size)
{
    const float* x = (const float*)d_in[0];
    const float* W = (const float*)d_in[1];
    const int T = in_sizes[0] / 2048;

    wprep_kernel<<<128, 256>>>(W);

    cudaFuncSetAttribute(router_kernel,
                         cudaFuncAttributeMaxDynamicSharedMemorySize, SMEMB);
    const int blocks = (T + TM - 1) / TM;
    router_kernel<<<blocks, THREADS, SMEMB>>>(x, (float*)d_out, T);
}

// round 15
// speedup vs baseline: 2.2604x; 2.2604x over previous
#include <cuda_runtime.h>
#include <cstdint>

// Router: logits = x @ W^T via split-fp16 mma.sync:
//   hh term    -> m16n8k16 f32-accum
//   cross terms-> m16n8k16 f16-accum (both into one accumulator, lo pre-scaled 2^12)
// logit = hh + 2^-12 * cross.  W pre-split once per launch.
// Outputs fp32: mask[T*64] | idx[T*2] | router_probs[T*64] | probs[T*64]

#define THREADS 128
#define TM 64             // tokens per CTA
#define CK 64             // K chunk
#define NCH (2048 / CK)   // 32
#define ASTR 144          // smem row stride bytes (64 fp16 = 128B + 16 pad)

// per-buffer smem layout (bytes): A hi/lo 64 rows, B hi/lo 64 rows
#define AHI_O 0
#define ALO_O 9216        // 64*144
#define BHI_O 18432
#define BLO_O 27648
#define BUFSZ 36864
#define SMEMB (2 * BUFSZ)
#define LS 68             // logits row stride (floats)
#define SC 2.44140625e-4f // 2^-12

typedef unsigned long long ull;

__device__ unsigned short g_Whi[64 * 2048];   // f16(w)
__device__ unsigned short g_Wlo[64 * 2048];   // f16((w - f16(w)) * 4096)

__device__ __forceinline__ uint32_t smem_u32(const void* p) {
    uint32_t a;
    asm("{ .reg .u64 t; cvta.to.shared.u64 t, %1; cvt.u32.u64 %0, t; }"
        : "=r"(a) : "l"(p));
    return a;
}

__device__ __forceinline__ void ldm4(uint32_t* r, uint32_t addr) {
    asm volatile("ldmatrix.sync.aligned.m8n8.x4.shared.b16 {%0,%1,%2,%3}, [%4];"
        : "=r"(r[0]), "=r"(r[1]), "=r"(r[2]), "=r"(r[3]) : "r"(addr));
}

// f32-accum fp16 MMA (hh term)
__device__ __forceinline__ void mma_f32(float* d, const uint32_t* a,
                                        uint32_t b0, uint32_t b1) {
    asm("mma.sync.aligned.m16n8k16.row.col.f32.f16.f16.f32 "
        "{%0,%1,%2,%3}, {%4,%5,%6,%7}, {%8,%9}, {%0,%1,%2,%3};"
        : "+f"(d[0]), "+f"(d[1]), "+f"(d[2]), "+f"(d[3])
        : "r"(a[0]), "r"(a[1]), "r"(a[2]), "r"(a[3]), "r"(b0), "r"(b1));
}

// f16-accum fp16 MMA (cross terms) — possibly double-rate
__device__ __forceinline__ void mma_f16(uint32_t* d, const uint32_t* a,
                                        uint32_t b0, uint32_t b1) {
    asm("mma.sync.aligned.m16n8k16.row.col.f16.f16.f16.f16 "
        "{%0,%1}, {%2,%3,%4,%5}, {%6,%7}, {%0,%1};"
        : "+r"(d[0]), "+r"(d[1])
        : "r"(a[0]), "r"(a[1]), "r"(a[2]), "r"(a[3]), "r"(b0), "r"(b1));
}

// f32 pair -> f16x2 hi  and  f16x2 lo' = (v - hi)*4096
__device__ __forceinline__ void split2h(float2 v, uint32_t& hi, uint32_t& lo) {
    asm("cvt.rn.f16x2.f32 %0, %1, %2;" : "=r"(hi) : "f"(v.y), "f"(v.x));
    float h0, h1;
    asm("{ .reg .f16 a, b; mov.b32 {a, b}, %2; cvt.f32.f16 %0, a; cvt.f32.f16 %1, b; }"
        : "=f"(h0), "=f"(h1) : "r"(hi));
    const float l0 = (v.x - h0) * 4096.f;
    const float l1 = (v.y - h1) * 4096.f;
    asm("cvt.rn.f16x2.f32 %0, %1, %2;" : "=r"(lo) : "f"(l1), "f"(l0));
}

__device__ __forceinline__ void split4h(float4 v, ull& H, ull& L) {
    uint32_t h0, h1, l0, l1;
    split2h(make_float2(v.x, v.y), h0, l0);
    split2h(make_float2(v.z, v.w), h1, l1);
    asm("mov.b64 %0, {%1, %2};" : "=l"(H) : "r"(h0), "r"(h1));
    asm("mov.b64 %0, {%1, %2};" : "=l"(L) : "r"(l0), "r"(l1));
}

__device__ __forceinline__ void cvt_store(uint32_t hi_addr, uint32_t lo_addr, float4 v) {
    ull H, L;
    split4h(v, H, L);
    asm volatile("st.shared.b64 [%0], %1;" :: "r"(hi_addr), "l"(H) : "memory");
    asm volatile("st.shared.b64 [%0], %1;" :: "r"(lo_addr), "l"(L) : "memory");
}

// unpack f16x2 -> two floats (x = low half)
__device__ __forceinline__ float2 h2f(uint32_t h) {
    float a, b;
    asm("{ .reg .f16 x, y; mov.b32 {x, y}, %2; cvt.f32.f16 %0, x; cvt.f32.f16 %1, y; }"
        : "=f"(a), "=f"(b) : "r"(h));
    return make_float2(a, b);
}

// ---- pre-kernel: split W (64x2048 fp32) -> f16 hi / scaled lo ----
__global__ void __launch_bounds__(256)
wprep_kernel(const float* __restrict__ W)
{
    const int i = blockIdx.x * 256 + threadIdx.x;   // 0..32767 float4s
    const float4 v = reinterpret_cast<const float4*>(W)[i];
    ull H, L;
    split4h(v, H, L);
    reinterpret_cast<ull*>(g_Whi)[i] = H;
    reinterpret_cast<ull*>(g_Wlo)[i] = L;
}

__global__ void __launch_bounds__(THREADS, 2)
router_kernel(const float* __restrict__ x, float* __restrict__ out, int T)
{
    extern __shared__ __align__(128) char dsm[];
    const uint32_t sb = smem_u32(dsm);

    const int tid = threadIdx.x;
    const int wid = tid >> 5;      // 0..3
    const int lane = tid & 31;
    const int row0 = blockIdx.x * TM;

    float4 ax[8];                  // A: 64 rows x 16 float4 = 1024 = 8*128
    uint4 bh[4], bl[4];            // B: 64 rows x 8 uint4 = 512 = 4*128
    float d[8][4];
    uint32_t cr[8][2];
#pragma unroll
    for (int t = 0; t < 8; t++) {
#pragma unroll
        for (int j = 0; j < 4; j++) d[t][j] = 0.f;
        cr[t][0] = 0u; cr[t][1] = 0u;
    }

    // ---- prologue: chunk 0 ----
#pragma unroll
    for (int i = 0; i < 8; i++) {
        const int f = i * THREADS + tid;           // 0..1023
        const int grow = row0 + (f >> 4);          // rows 0..63
        ax[i] = (grow < T)
            ? *reinterpret_cast<const float4*>(x + (size_t)grow * 2048 + (f & 15) * 4)
            : make_float4(0.f, 0.f, 0.f, 0.f);
    }
#pragma unroll
    for (int i = 0; i < 4; i++) {
        const int f = i * THREADS + tid;           // 0..511
        const int rr = f >> 3;                     // 0..63
        const int cc = f & 7;                      // uint4 col
        bh[i] = *reinterpret_cast<const uint4*>(g_Whi + (size_t)rr * 2048 + cc * 8);
        bl[i] = *reinterpret_cast<const uint4*>(g_Wlo + (size_t)rr * 2048 + cc * 8);
    }
    {
#pragma unroll
        for (int i = 0; i < 8; i++) {
            const int f = i * THREADS + tid;
            const uint32_t o = (uint32_t)((f >> 4) * ASTR + (f & 15) * 8);
            cvt_store(sb + AHI_O + o, sb + ALO_O + o, ax[i]);
        }
#pragma unroll
        for (int i = 0; i < 4; i++) {
            const int f = i * THREADS + tid;
            const uint32_t o = (uint32_t)((f >> 3) * ASTR + (f & 7) * 16);
            *reinterpret_cast<uint4*>(dsm + BHI_O + o) = bh[i];
            *reinterpret_cast<uint4*>(dsm + BLO_O + o) = bl[i];
        }
    }
    __syncthreads();

    // ldmatrix per-lane offsets (identical to the passing round-7 layout)
    const uint32_t a_off = (uint32_t)((wid * 16 + (lane & 15)) * ASTR + ((lane >> 4) << 4));
    const uint32_t b_off = (uint32_t)((((lane & 7) + ((lane >> 4) & 1) * 8)) * ASTR
                                      + (((lane >> 3) & 1) << 4));

    for (int c = 0; c < NCH; c++) {
        // register prefetch of next chunk
        if (c + 1 < NCH) {
            const int k0 = (c + 1) * CK;
#pragma unroll
            for (int i = 0; i < 8; i++) {
                const int f = i * THREADS + tid;
                const int grow = row0 + (f >> 4);
                if (grow < T)
                    ax[i] = *reinterpret_cast<const float4*>(
                        x + (size_t)grow * 2048 + k0 + (f & 15) * 4);
            }
#pragma unroll
            for (int i = 0; i < 4; i++) {
                const int f = i * THREADS + tid;
                const int rr = f >> 3;
                const int cc = f & 7;
                bh[i] = *reinterpret_cast<const uint4*>(
                    g_Whi + (size_t)rr * 2048 + k0 + cc * 8);
                bl[i] = *reinterpret_cast<const uint4*>(
                    g_Wlo + (size_t)rr * 2048 + k0 + cc * 8);
            }
        }

        // ---- compute on current buffer ----
        {
            const uint32_t tb = sb + (uint32_t)(c & 1) * BUFSZ;
#pragma unroll
            for (int kk = 0; kk < 4; kk++) {
                const uint32_t ko = kk * 32;  // 16 fp16 = 32 bytes
                uint32_t ah[4], al[4];
                ldm4(ah, tb + AHI_O + a_off + ko);
                ldm4(al, tb + ALO_O + a_off + ko);
#pragma unroll
                for (int j = 0; j < 4; j++) {
                    uint32_t vh[4], vl[4];
                    const uint32_t bo = (uint32_t)(j * 16 * ASTR) + b_off + ko;
                    ldm4(vh, tb + BHI_O + bo);
                    ldm4(vl, tb + BLO_O + bo);
#pragma unroll
                    for (int tt = 0; tt < 2; tt++) {
                        mma_f32(d[j * 2 + tt], ah, vh[tt * 2], vh[tt * 2 + 1]);
                        mma_f16(cr[j * 2 + tt], ah, vl[tt * 2], vl[tt * 2 + 1]);
                        mma_f16(cr[j * 2 + tt], al, vh[tt * 2], vh[tt * 2 + 1]);
                    }
                }
            }
        }

        // ---- store next chunk into other buffer ----
        if (c + 1 < NCH) {
            const uint32_t off = (uint32_t)((c + 1) & 1) * BUFSZ;
            const uint32_t tb = sb + off;
#pragma unroll
            for (int i = 0; i < 8; i++) {
                const int f = i * THREADS + tid;
                const uint32_t o = (uint32_t)((f >> 4) * ASTR + (f & 15) * 8);
                cvt_store(tb + AHI_O + o, tb + ALO_O + o, ax[i]);
            }
#pragma unroll
            for (int i = 0; i < 4; i++) {
                const int f = i * THREADS + tid;
                const uint32_t o = (uint32_t)((f >> 3) * ASTR + (f & 7) * 16);
                *reinterpret_cast<uint4*>(dsm + off + BHI_O + o) = bh[i];
                *reinterpret_cast<uint4*>(dsm + off + BLO_O + o) = bl[i];
            }
        }
        __syncthreads();
    }

    // ---- combine hh + 2^-12*cross, dump logits to smem [TM][LS] ----
    float* lg = reinterpret_cast<float*>(dsm);
    {
        const int r1 = wid * 16 + (lane >> 2);   // 0..63
        const int n0 = (lane & 3) * 2;
#pragma unroll
        for (int t = 0; t < 8; t++) {
            const float2 c0 = h2f(cr[t][0]);
            const float2 c1 = h2f(cr[t][1]);
            *reinterpret_cast<float2*>(lg + r1 * LS + t * 8 + n0) =
                make_float2(d[t][0] + SC * c0.x, d[t][1] + SC * c0.y);
            *reinterpret_cast<float2*>(lg + (r1 + 8) * LS + t * 8 + n0) =
                make_float2(d[t][2] + SC * c1.x, d[t][3] + SC * c1.y);
        }
    }
    __syncthreads();

    // ---- epilogue: one thread = one token (threads 0..63) ----
    if (tid >= TM) return;
    const int row = row0 + tid;
    if (row >= T) return;

    float l[64];
#pragma unroll
    for (int e = 0; e < 64; e += 4) {
        const float4 v = *reinterpret_cast<const float4*>(lg + tid * LS + e);
        l[e] = v.x; l[e + 1] = v.y; l[e + 2] = v.z; l[e + 3] = v.w;
    }

    // top-2 (earliest index wins ties, matching lax.top_k)
    float m1 = -3.402823466e38f, m2 = -3.402823466e38f;
    int i1 = 0, i2 = 0;
#pragma unroll
    for (int e = 0; e < 64; e++) {
        const float v = l[e];
        if (v > m1) { m2 = m1; i2 = i1; m1 = v; i1 = e; }
        else if (v > m2) { m2 = v; i2 = e; }
    }

    float s = 0.f;
    float p[64];
#pragma unroll
    for (int e = 0; e < 64; e++) {
        p[e] = __expf(l[e] - m1);
        s += p[e];
    }
    const float inv = 1.0f / s;

    const float p1 = p[i1] * inv;
    const float p2 = p[i2] * inv;
    const float rs = 1.0f / (p1 + p2);

    const size_t Tz = (size_t)T;
    float* mask = out;
    float* idxo = out + Tz * 64;
    float* rp   = out + Tz * 64 + Tz * 2;
    float* pr   = out + Tz * 64 + Tz * 2 + Tz * 64;
    const size_t gt = (size_t)row;

#pragma unroll
    for (int e = 0; e < 64; e += 4) {
        float4 pv4, m4, r4;
        float* pvp = &pv4.x; float* mp = &m4.x; float* rpp = &r4.x;
#pragma unroll
        for (int j = 0; j < 4; j++) {
            const int ee = e + j;
            const float pv = p[ee] * inv;
            const bool sel = (ee == i1) | (ee == i2);
            pvp[j] = pv;
            mp[j] = sel ? 1.0f : 0.0f;
            rpp[j] = sel ? pv * rs : 0.0f;
        }
        *reinterpret_cast<float4*>(pr + gt * 64 + e) = pv4;
        *reinterpret_cast<float4*>(mask + gt * 64 + e) = m4;
        *reinterpret_cast<float4*>(rp + gt * 64 + e) = r4;
    }
    idxo[gt * 2 + 0] = (float)i1;
    idxo[gt * 2 + 1] = (float)i2;
}

extern "C" void kernel_launch(void* const* d_in, const int* in_sizes, int n_in,
                              void* d_out, int out_size)
{
    const float* x = (const float*)d_in[0];
    const float* W = (const float*)d_in[1];
    const int T = in_sizes[0] / 2048;

    wprep_kernel<<<128, 256>>>(W);

    cudaFuncSetAttribute(router_kernel,
                         cudaFuncAttributeMaxDynamicSharedMemorySize, SMEMB);
    const int blocks = (T + TM - 1) / TM;
    router_kernel<<<blocks, THREADS, SMEMB>>>(x, (float*)d_out, T);
}